// round 3
// baseline (speedup 1.0000x reference)
#include <cuda_runtime.h>
#include <cstdint>
#include <cstddef>

#define NB     32
#define NLAT   721
#define NLON   1440
#define NVEC   360          // NLON / 4
#define NWORDS 45           // NLON / 32
#define NTH    128

// Cross-kernel scratch (no allocations allowed).
__device__ int g_lastrow[NB];

__global__ void init_kernel() {
    if (threadIdx.x < NB) g_lastrow[threadIdx.x] = -1;
}

__device__ __forceinline__ bool nan_f(float x) {
    return (__float_as_uint(x) & 0x7FFFFFFFu) > 0x7F800000u;
}

// Butterfly-combine 4-bit validity nibbles across groups of 8 lanes into a
// 32-bit mask word (bit 4k+j = validity of element 4*(group_base+k)+j).
__device__ __forceinline__ unsigned combine8(unsigned v, int lane) {
    unsigned o = __shfl_xor_sync(0xFFFFFFFFu, v, 1);
    v = (lane & 1) ? ((v << 4) | o) : ((o << 4) | v);
    o = __shfl_xor_sync(0xFFFFFFFFu, v, 2);
    v = (lane & 2) ? ((v << 8) | o) : ((o << 8) | v);
    o = __shfl_xor_sync(0xFFFFFFFFu, v, 4);
    v = (lane & 4) ? ((v << 16) | o) : ((o << 16) | v);
    return v;
}

__device__ __forceinline__ unsigned nib_of(float4 r) {
    return (unsigned)(!nan_f(r.x))        | ((unsigned)(!nan_f(r.y)) << 1)
         | ((unsigned)(!nan_f(r.z)) << 2) | ((unsigned)(!nan_f(r.w)) << 3);
}

// Interp one NaN element i given 64-bit low/high windows around its word.
// lo64 = (mask[w]<<32)|mask[w-1], hi64 = (mask[w+1]<<32)|mask[w].
__device__ __forceinline__ float interp_elem(
    int i, int w, unsigned long long lo64, unsigned long long hi64,
    const unsigned* __restrict__ mask, const float* __restrict__ s,
    int firstv, int lastv)
{
    const int bpos = i & 31;

    // prev: largest valid j <= i
    unsigned long long lm = lo64 & (0xFFFFFFFFFFFFFFFFull >> (31 - bpos));
    int prev;
    if (lm) {
        prev = ((w - 1) << 5) + 63 - __clzll(lm);
    } else {
        prev = lastv - NLON;                        // circular wrap
        #pragma unroll 1
        for (int ww = w - 2; ww >= 0; ww--) {
            unsigned mw = mask[ww];
            if (mw) { prev = (ww << 5) + 31 - __clz(mw); break; }
        }
    }

    // next: smallest valid j >= i
    unsigned long long hm = hi64 & (0xFFFFFFFFFFFFFFFFull << bpos);
    int nxt;
    if (hm) {
        nxt = (w << 5) + __ffsll(hm) - 1;
    } else {
        nxt = firstv + NLON;                        // circular wrap
        #pragma unroll 1
        for (int ww = w + 2; ww < NWORDS; ww++) {
            unsigned mw = mask[ww];
            if (mw) { nxt = (ww << 5) + __ffs(mw) - 1; break; }
        }
    }

    const int dtot = nxt - prev;                    // provably > 0 when row valid
    const float t  = __fdividef((float)(i - prev), (float)dtot);
    const int pm = (prev < 0)     ? prev + NLON : prev;
    const int nm = (nxt >= NLON)  ? nxt  - NLON : nxt;
    const float sp = s[pm];
    const float sn = s[nm];
    return fmaf(t, sn - sp, sp);
}

// ---------------------------------------------------------------------------
// Kernel A: one 128-thread CTA per (b, lat) row. Single __syncthreads.
// ---------------------------------------------------------------------------
__global__ void __launch_bounds__(NTH)
fill_rows_kernel(const float4* __restrict__ sst4, float* __restrict__ out, int row0)
{
    const int row = row0 + blockIdx.x;              // b * NLAT + h
    const float4* __restrict__ src = sst4 + (size_t)row * NVEC;
    float4*       __restrict__ dst = (float4*)(out + (size_t)row * NLON);

    __shared__ float    s[NLON];
    __shared__ unsigned mask[NWORDS];

    const int t    = threadIdx.x;
    const int lane = t & 31;

    // ---- Front-batched loads (3 independent LDG.128) ----
    float4 r0 = src[t];
    float4 r1 = src[t + 128];
    float4 r2 = make_float4(0.f, 0.f, 0.f, 0.f);
    const bool has2 = (t < NVEC - 256);             // t < 104
    if (has2) r2 = src[t + 256];

    ((float4*)s)[t]       = r0;
    ((float4*)s)[t + 128] = r1;
    if (has2) ((float4*)s)[t + 256] = r2;

    // ---- Build validity mask from registers (no LDS, no ballots) ----
    unsigned w0 = combine8(nib_of(r0), lane);
    unsigned w1 = combine8(nib_of(r1), lane);
    unsigned w2 = combine8(has2 ? nib_of(r2) : 0u, lane);
    if ((lane & 7) == 0) {
        const int widx = t >> 3;                    // 0..15
        mask[widx]      = w0;
        mask[widx + 16] = w1;
        if (widx + 32 < NWORDS) mask[widx + 32] = w2;
    }
    __syncthreads();                                // the ONLY barrier

    // ---- first/last valid index: computed redundantly per warp ----
    const unsigned mwa = (lane < NWORDS)      ? mask[lane]      : 0u;
    const unsigned mwb = (lane + 32 < NWORDS) ? mask[lane + 32] : 0u;
    const unsigned b1 = __ballot_sync(0xFFFFFFFFu, mwa != 0u);
    const unsigned b2 = __ballot_sync(0xFFFFFFFFu, mwb != 0u);
    const bool rv = (b1 | b2) != 0u;

    int firstv = 0, lastv = 0;
    if (rv) {
        const int fw = b1 ? (__ffs(b1) - 1) : (31 + __ffs(b2));
        const unsigned fm = __shfl_sync(0xFFFFFFFFu, (fw < 32) ? mwa : mwb, fw & 31);
        firstv = (fw << 5) + __ffs(fm) - 1;
        const int lw = b2 ? (63 - __clz(b2)) : (31 - __clz(b1));
        const unsigned lm = __shfl_sync(0xFFFFFFFFu, (lw < 32) ? mwa : mwb, lw & 31);
        lastv = (lw << 5) + 31 - __clz(lm);
    }

    if (t == 0 && rv) {
        atomicMax(&g_lastrow[row / NLAT], row % NLAT);
    }

    // ---- Interpolate from registers + gather from SMEM, STG.128 out ----
    #pragma unroll
    for (int k = 0; k < 3; k++) {
        if (k == 2 && !has2) break;
        const int vec  = t + k * NTH;
        const int base = vec << 2;
        const int w    = base >> 5;
        float4 r = (k == 0) ? r0 : (k == 1) ? r1 : r2;

        if (rv) {
            const unsigned cur = mask[w];
            const unsigned lo  = (w > 0)          ? mask[w - 1] : 0u;
            const unsigned hi  = (w < NWORDS - 1) ? mask[w + 1] : 0u;
            const unsigned long long lo64 = ((unsigned long long)cur << 32) | lo;
            const unsigned long long hi64 = ((unsigned long long)hi  << 32) | cur;

            if (nan_f(r.x)) r.x = interp_elem(base + 0, w, lo64, hi64, mask, s, firstv, lastv);
            if (nan_f(r.y)) r.y = interp_elem(base + 1, w, lo64, hi64, mask, s, firstv, lastv);
            if (nan_f(r.z)) r.z = interp_elem(base + 2, w, lo64, hi64, mask, s, firstv, lastv);
            if (nan_f(r.w)) r.w = interp_elem(base + 3, w, lo64, hi64, mask, s, firstv, lastv);
        }
        dst[vec] = r;
    }
}

// ---------------------------------------------------------------------------
// Kernel B: polar fill. Common case: immediate exit (lastrow == NLAT-1).
// ---------------------------------------------------------------------------
__global__ void __launch_bounds__(256)
fill_polar_kernel(const float* __restrict__ sst, float* __restrict__ out)
{
    const int b = blockIdx.x;
    const int lastrow = g_lastrow[b];
    if (lastrow < 0 || lastrow >= NLAT - 1) return;

    const int tid = threadIdx.x;

    __shared__ float    s[NLON];
    __shared__ float    f[NLON];
    __shared__ unsigned mask[NWORDS];
    __shared__ int      s_first, s_last;

    const float* __restrict__ srow = sst + ((size_t)b * NLAT + lastrow) * NLON;

    for (int i = tid; i < NLON; i += 256) s[i] = srow[i];
    __syncthreads();

    #pragma unroll
    for (int k = 0; k < 6; k++) {
        const int i = k * 256 + tid;
        const bool inb = (i < NLON);
        const bool valid = inb && !nan_f(inb ? s[i] : 0.0f);
        const unsigned bal = __ballot_sync(0xFFFFFFFFu, valid);
        if ((tid & 31) == 0) {
            const int w = i >> 5;
            if (w < NWORDS) mask[w] = bal;
        }
    }
    __syncthreads();

    if (tid == 0) {
        int ff = -1, la = -1;
        #pragma unroll 1
        for (int w = 0; w < NWORDS; w++) {
            unsigned mw = mask[w];
            if (mw) { ff = (w << 5) + __ffs(mw) - 1; break; }
        }
        #pragma unroll 1
        for (int w = NWORDS - 1; w >= 0; w--) {
            unsigned mw = mask[w];
            if (mw) { la = (w << 5) + 31 - __clz(mw); break; }
        }
        s_first = ff; s_last = la;
    }
    __syncthreads();

    for (int i = tid; i < NLON; i += 256) {
        const int w = i >> 5;
        const unsigned cur = mask[w];
        const unsigned lo  = (w > 0)          ? mask[w - 1] : 0u;
        const unsigned hi  = (w < NWORDS - 1) ? mask[w + 1] : 0u;
        const unsigned long long lo64 = ((unsigned long long)cur << 32) | lo;
        const unsigned long long hi64 = ((unsigned long long)hi  << 32) | cur;
        f[i] = interp_elem(i, w, lo64, hi64, mask, s, s_first, s_last);
    }
    __syncthreads();

    for (int h = lastrow + 1; h < NLAT; h++) {
        const float* __restrict__ sr   = sst + ((size_t)b * NLAT + h) * NLON;
        float*       __restrict__ orow = out + ((size_t)b * NLAT + h) * NLON;
        for (int i = tid; i < NLON; i += 256) {
            if (nan_f(sr[i])) orow[i] = f[i];
        }
    }
}

// ---------------------------------------------------------------------------
extern "C" void kernel_launch(void* const* d_in, const int* in_sizes, int n_in,
                              void* d_out, int out_size)
{
    const float* sst = (const float*)d_in[0];
    float*       out = (float*)d_out;

    const int half = (NB * NLAT + 1) / 2;           // 11536
    init_kernel<<<1, 32>>>();
    fill_rows_kernel<<<half, NTH>>>((const float4*)sst, out, 0);
    fill_rows_kernel<<<NB * NLAT - half, NTH>>>((const float4*)sst, out, half);
    fill_polar_kernel<<<NB, 256>>>(sst, out);
}